// round 1
// baseline (speedup 1.0000x reference)
#include <cuda_runtime.h>

#define MDIM 1024
#define GR   16          // batch rows per block
#define TPB  256
#define SMEM_BYTES (3*MDIM*GR*4 + MDIM*16 + MDIM*16)   // buf + wsig(float4) + idx(int4) = 229376

// ---------------- schedule scratch (no allocations allowed) ----------------
__device__ int d_sched[MDIM];
__device__ int d_off[MDIM + 2];

// ---------------------------------------------------------------------------
// Kernel 1: compute dataflow levels of the 1024-step DAG and a level-sorted
// schedule. Parents of step i are the carry-type gathers (raw >= M). Depth of
// this random DAG is ~60-90, so parallel relaxation converges fast.
// ---------------------------------------------------------------------------
__global__ void sched_kernel(const int* __restrict__ raw) {
    __shared__ int lvl[MDIM];
    __shared__ int cnt[MDIM];
    __shared__ int sc[MDIM];
    __shared__ int cur[MDIM];
    __shared__ int changed;

    int i = threadIdx.x;
    int p0 = raw[2*i];
    int p1 = raw[2*i + 1];
    int p2 = raw[2*MDIM + 2*i];
    int p3 = raw[2*MDIM + 2*i + 1];

    lvl[i] = 0;
    for (;;) {
        if (i == 0) changed = 0;
        __syncthreads();                       // init/reset + prior writes visible
        int curL = lvl[i];
        int nl = curL;
        if (p0 >= MDIM) nl = max(nl, lvl[p0 & (MDIM-1)] + 1);
        if (p1 >= MDIM) nl = max(nl, lvl[p1 & (MDIM-1)] + 1);
        if (p2 >= MDIM) nl = max(nl, lvl[p2 & (MDIM-1)] + 1);
        if (p3 >= MDIM) nl = max(nl, lvl[p3 & (MDIM-1)] + 1);
        __syncthreads();                       // all reads done before writes
        if (nl > curL) { lvl[i] = nl; changed = 1; }
        __syncthreads();                       // writes + changed final
        if (!changed) break;
    }

    // counting sort by level
    cnt[i] = 0;
    __syncthreads();
    atomicAdd(&cnt[lvl[i]], 1);
    __syncthreads();
    sc[i] = cnt[i];
    __syncthreads();
    for (int d = 1; d < MDIM; d <<= 1) {       // inclusive Hillis-Steele scan
        int add = (i >= d) ? sc[i - d] : 0;
        __syncthreads();
        sc[i] += add;
        __syncthreads();
    }
    int excl = sc[i] - cnt[i];
    d_off[i] = excl;
    if (i == 0) d_off[MDIM] = MDIM;
    cur[i] = excl;
    __syncthreads();
    int pos = atomicAdd(&cur[lvl[i]], 1);      // within-level order arbitrary: values
    d_sched[pos] = i;                          // are independent of within-level order
}

// ---------------------------------------------------------------------------
// Kernel 2: one block processes GR=16 batch rows entirely in shared memory.
// SMEM buf is laid out [x(1024) | plus(1024) | prod(1024)] x 16 rows so that a
// gather with raw index in [0, 3M) is a single LDS: buf[raw*16 + g].
// Levels execute wide (level_size * 16 items over 256 threads), barrier per
// level. Epilogue computes the three dot products per row.
// ---------------------------------------------------------------------------
__global__ void __launch_bounds__(TPB, 1)
tree_kernel(const float* __restrict__ x,      const int*   __restrict__ raw,
            const float* __restrict__ W_base, const float* __restrict__ b_base,
            const float* __restrict__ W_sig,  const float* __restrict__ b_sig,
            const float* __restrict__ w_plus, const float* __restrict__ b_plus,
            const float* __restrict__ w_prod, const float* __restrict__ b_prod,
            float* __restrict__ out)
{
    extern __shared__ float sm[];
    float* buf  = sm;                                    // [3*M][GR]
    float4* wsg = (float4*)(sm + 3*MDIM*GR);             // [M] (w0,w1,bs,-)
    int4*  idxs = (int4*) (sm + 3*MDIM*GR + 4*MDIM);     // [M] (a0,a1,p0,p1)

    int tid = threadIdx.x;
    int rowBase = blockIdx.x * GR;

    // stage x rows (coalesced gmem read, transposed into [m][g])
    for (int k = tid; k < MDIM*GR; k += TPB) {
        int g = k >> 10, m = k & (MDIM-1);
        buf[m*GR + g] = x[(rowBase + g)*MDIM + m];
    }
    // stage per-step weights and gather indices
    for (int i = tid; i < MDIM; i += TPB) {
        float4 w;
        w.x = W_sig[2*i]; w.y = W_sig[2*i + 1]; w.z = b_sig[i]; w.w = 0.f;
        wsg[i] = w;
        int4 v;
        v.x = raw[2*i];          v.y = raw[2*i + 1];
        v.z = raw[2*MDIM + 2*i]; v.w = raw[2*MDIM + 2*i + 1];
        idxs[i] = v;
    }
    __syncthreads();

    // level-parallel recurrence
    for (int L = 0;; ++L) {
        int start = d_off[L];
        if (start >= MDIM) break;
        int end = d_off[L + 1];
        int n = (end - start) * GR;
        for (int k = tid; k < n; k += TPB) {
            int s = d_sched[start + (k >> 4)];
            int g = k & (GR - 1);
            int4 v = idxs[s];
            float a0 = buf[v.x*GR + g];
            float a1 = buf[v.y*GR + g];
            float b0 = buf[v.z*GR + g];
            float b1 = buf[v.w*GR + g];
            float4 w = wsg[s];
            float z = fmaf(w.x, a0, fmaf(w.y, a1, w.z));
            float pl = 1.0f / (1.0f + __expf(-z));
            buf[(MDIM   + s)*GR + g] = pl;        // plus
            buf[(2*MDIM + s)*GR + g] = b0 * b1;   // prod
        }
        __syncthreads();
    }

    // epilogue: out[b] = x.Wb + plus.wp + prod.wq + biases
    int g = tid & (GR - 1), seg = tid >> 4;
    float acc = 0.f;
    for (int m = seg; m < MDIM; m += 16) {
        acc += buf[m*GR + g]          * W_base[m]
             + buf[(MDIM   + m)*GR + g] * w_plus[m]
             + buf[(2*MDIM + m)*GR + g] * w_prod[m];
    }
    float* red = (float*)wsg;   // safe to reuse: all wsg reads are pre-barrier
    red[g*17 + seg] = acc;
    __syncthreads();
    if (tid < GR) {
        float t = 0.f;
        #pragma unroll
        for (int s = 0; s < 16; s++) t += red[tid*17 + s];
        out[rowBase + tid] = t + b_base[0] + b_plus[0] + b_prod[0];
    }
}

// ---------------------------------------------------------------------------
extern "C" void kernel_launch(void* const* d_in, const int* in_sizes, int n_in,
                              void* d_out, int out_size) {
    const float* x  = (const float*)d_in[0];
    const int*   ri = (const int*)  d_in[1];
    const float* Wb = (const float*)d_in[2];
    const float* bb = (const float*)d_in[3];
    const float* Ws = (const float*)d_in[4];
    const float* bs = (const float*)d_in[5];
    const float* wp = (const float*)d_in[6];
    const float* bp = (const float*)d_in[7];
    const float* wq = (const float*)d_in[8];
    const float* bq = (const float*)d_in[9];
    float* out = (float*)d_out;

    int B = in_sizes[0] / MDIM;   // 8192

    cudaFuncSetAttribute(tree_kernel,
                         cudaFuncAttributeMaxDynamicSharedMemorySize, SMEM_BYTES);

    sched_kernel<<<1, MDIM>>>(ri);
    tree_kernel<<<B / GR, TPB, SMEM_BYTES>>>(x, ri, Wb, bb, Ws, bs, wp, bp, wq, bq, out);
}

// round 2
// speedup vs baseline: 2.0951x; 2.0951x over previous
#include <cuda_runtime.h>

#define MDIM 1024
#define GR   16          // batch rows per block = warps per block
#define TPB  512
#define ROWSTRIDE (3*MDIM)
#define SMEM_BYTES (GR*ROWSTRIDE*4 + MDIM*16 + MDIM*16)   // buf 192K + idx4 16K + w4 16K = 229376

// ---------------- schedule scratch (no allocations allowed) ----------------
__device__ int    d_off[MDIM + 2];
__device__ int4   d_pidx[MDIM];    // level-sorted parent tuples (a0,a1,p0,p1)
__device__ float4 d_pw[MDIM];      // level-sorted (w0, w1, b_sig, step-id as bits)
__device__ int    d_nlev;

// ---------------------------------------------------------------------------
// Kernel 1: dataflow levels of the 1024-step DAG + level-sorted packed
// schedule (parents, weights, destination step). Monotone relaxation with
// benign races (word-atomic, monotone-increasing) converges in <= depth iters.
// ---------------------------------------------------------------------------
__global__ void sched_kernel(const int* __restrict__ raw,
                             const float* __restrict__ W_sig,
                             const float* __restrict__ b_sig) {
    __shared__ int lvl[MDIM];
    __shared__ int cnt[MDIM];
    __shared__ int sc[MDIM];
    __shared__ int cur[MDIM];
    __shared__ int changed;
    __shared__ int maxl;

    int i = threadIdx.x;
    int p0 = raw[2*i];
    int p1 = raw[2*i + 1];
    int p2 = raw[2*MDIM + 2*i];
    int p3 = raw[2*MDIM + 2*i + 1];

    lvl[i] = 0;
    if (i == 0) maxl = 0;
    __syncthreads();
    for (;;) {
        if (i == 0) changed = 0;
        __syncthreads();
        int nl = lvl[i];
        if (p0 >= MDIM) nl = max(nl, lvl[p0 & (MDIM-1)] + 1);
        if (p1 >= MDIM) nl = max(nl, lvl[p1 & (MDIM-1)] + 1);
        if (p2 >= MDIM) nl = max(nl, lvl[p2 & (MDIM-1)] + 1);
        if (p3 >= MDIM) nl = max(nl, lvl[p3 & (MDIM-1)] + 1);
        if (nl > lvl[i]) { lvl[i] = nl; changed = 1; }   // benign race, monotone
        __syncthreads();
        if (!changed) break;
    }

    int L = lvl[i];
    atomicMax(&maxl, L);

    // counting sort by level
    cnt[i] = 0;
    __syncthreads();
    atomicAdd(&cnt[L], 1);
    __syncthreads();
    sc[i] = cnt[i];
    __syncthreads();
    for (int d = 1; d < MDIM; d <<= 1) {       // inclusive Hillis-Steele scan
        int add = (i >= d) ? sc[i - d] : 0;
        __syncthreads();
        sc[i] += add;
        __syncthreads();
    }
    int excl = sc[i] - cnt[i];
    d_off[i] = excl;
    cur[i] = excl;
    if (i == 0) { d_off[MDIM] = MDIM; d_off[MDIM+1] = MDIM; d_nlev = maxl + 1; }
    __syncthreads();

    // scatter packed schedule (within-level order arbitrary: parents are in
    // strictly lower levels, values independent of within-level order)
    int pos = atomicAdd(&cur[L], 1);
    d_pidx[pos] = make_int4(p0, p1, p2, p3);
    float4 w;
    w.x = W_sig[2*i]; w.y = W_sig[2*i + 1]; w.z = b_sig[i];
    w.w = __int_as_float(i);
    d_pw[pos] = w;
}

// ---------------------------------------------------------------------------
// Kernel 2: one WARP owns one batch row end-to-end. 16 warps = 16 rows per
// block, entire carry [x|plus|prod] for the row in SMEM (12KB/row). Main loop
// has ZERO block-wide barriers: per-level __syncwarp only, with next-level
// schedule prefetched before the sync. Persistent blocks loop over row-groups.
// ---------------------------------------------------------------------------
__global__ void __launch_bounds__(TPB, 1)
tree_kernel(const float* __restrict__ x,
            const float* __restrict__ W_base, const float* __restrict__ b_base,
            const float* __restrict__ w_plus, const float* __restrict__ b_plus,
            const float* __restrict__ w_prod, const float* __restrict__ b_prod,
            float* __restrict__ out, int nGroups)
{
    extern __shared__ char smraw[];
    float* buf  = (float*)smraw;                                  // [GR][3*M]
    int4*  sIdx = (int4*) (smraw + GR*ROWSTRIDE*4);               // [M]
    float4* sW  = (float4*)(smraw + GR*ROWSTRIDE*4 + MDIM*16);    // [M]

    int tid  = threadIdx.x;
    int lane = tid & 31;
    int wrow = tid >> 5;                 // warp id = row within group (0..15)

    // stage packed schedule once per block
    for (int i = tid; i < MDIM; i += TPB) { sIdx[i] = d_pidx[i]; sW[i] = d_pw[i]; }
    __syncthreads();                     // the ONLY block-wide barrier

    const int nLev = d_nlev;
    float* rb = buf + wrow * ROWSTRIDE;
    float bias = b_base[0] + b_plus[0] + b_prod[0];

    for (int grp = blockIdx.x; grp < nGroups; grp += gridDim.x) {
        int row = grp * GR + wrow;

        // warp stages its own x row (coalesced float4)
        const float4* xr = (const float4*)(x + (size_t)row * MDIM);
        #pragma unroll
        for (int k = 0; k < MDIM/128; k++) {
            ((float4*)rb)[lane + 32*k] = xr[lane + 32*k];
        }
        __syncwarp();

        // level-parallel recurrence, schedule prefetched one level ahead
        int s0 = 0;
        int s1 = d_off[1];
        int4  v; float4 w;
        if (lane < s1) { v = sIdx[lane]; w = sW[lane]; }

        for (int L = 0; L < nLev; L++) {
            int s2 = d_off[L + 2];               // rolled ahead (off chain)
            int n = s1 - s0;
            if (lane < n) {                       // chunk 0: prefetched
                int s = __float_as_int(w.w);
                float a0 = rb[v.x], a1 = rb[v.y];
                float b0 = rb[v.z], b1 = rb[v.w];
                float z  = fmaf(w.x, a0, fmaf(w.y, a1, w.z));
                float pl = __fdividef(1.0f, 1.0f + __expf(-z));
                rb[MDIM     + s] = pl;            // plus
                rb[2*MDIM   + s] = b0 * b1;       // prod
            }
            for (int base = s0 + 32; base < s1; base += 32) {   // rare spill chunks
                int p = base + lane;
                if (p < s1) {
                    int4 v2 = sIdx[p]; float4 w2 = sW[p];
                    int s = __float_as_int(w2.w);
                    float a0 = rb[v2.x], a1 = rb[v2.y];
                    float b0 = rb[v2.z], b1 = rb[v2.w];
                    float z  = fmaf(w2.x, a0, fmaf(w2.y, a1, w2.z));
                    float pl = __fdividef(1.0f, 1.0f + __expf(-z));
                    rb[MDIM   + s] = pl;
                    rb[2*MDIM + s] = b0 * b1;
                }
            }
            int nn = s2 - s1;                     // prefetch next level chunk 0
            if (lane < nn) { v = sIdx[s1 + lane]; w = sW[s1 + lane]; }
            __syncwarp();
            s0 = s1; s1 = s2;
        }

        // epilogue: warp-private triple dot product, stride-32 (conflict-free)
        float acc = 0.0f;
        for (int m = lane; m < MDIM; m += 32) {
            acc = fmaf(rb[m],          W_base[m],
                  fmaf(rb[MDIM + m],   w_plus[m],
                  fmaf(rb[2*MDIM + m], w_prod[m], acc)));
        }
        #pragma unroll
        for (int o = 16; o; o >>= 1) acc += __shfl_xor_sync(0xFFFFFFFFu, acc, o);
        if (lane == 0) out[row] = acc + bias;
        __syncwarp();   // row buffer is warp-private; safe to restage next group
    }
}

// ---------------------------------------------------------------------------
extern "C" void kernel_launch(void* const* d_in, const int* in_sizes, int n_in,
                              void* d_out, int out_size) {
    const float* x  = (const float*)d_in[0];
    const int*   ri = (const int*)  d_in[1];
    const float* Wb = (const float*)d_in[2];
    const float* bb = (const float*)d_in[3];
    const float* Ws = (const float*)d_in[4];
    const float* bs = (const float*)d_in[5];
    const float* wp = (const float*)d_in[6];
    const float* bp = (const float*)d_in[7];
    const float* wq = (const float*)d_in[8];
    const float* bq = (const float*)d_in[9];
    float* out = (float*)d_out;

    int B = in_sizes[0] / MDIM;          // 8192
    int nGroups = B / GR;                // 512

    static int sm_count = 0;
    if (sm_count == 0) {
        int dev = 0;
        cudaGetDevice(&dev);
        cudaDeviceGetAttribute(&sm_count, cudaDevAttrMultiProcessorCount, dev);
        if (sm_count <= 0) sm_count = 148;
        cudaFuncSetAttribute(tree_kernel,
                             cudaFuncAttributeMaxDynamicSharedMemorySize, SMEM_BYTES);
    }
    int grid = nGroups < sm_count ? nGroups : sm_count;

    sched_kernel<<<1, MDIM>>>(ri, Ws, bs);
    tree_kernel<<<grid, TPB, SMEM_BYTES>>>(x, Wb, bb, wp, bp, wq, bq, out, nGroups);
}